// round 2
// baseline (speedup 1.0000x reference)
#include <cuda_runtime.h>
#include <cstdint>

// Problem constants (fixed shapes per reference)
#define BATCH 4
#define NNODES 4096          // N
#define CH 96                // C
#define N1 (NNODES + 1)      // 4097
#define PS 4                 // pooling_patch_size
#define NPATCH (NNODES / PS) // 1024
// tk = ps / reduction_ratio = 1

// Scratch: v[b][m] = sum_c sigmoid(nodes[b,m,c]) * theta[c]
__device__ float g_v[BATCH * NNODES];

__device__ __forceinline__ float fsig(float x) {
    // fast sigmoid: ~1e-7 rel err (EX2 + RCP on MUFU)
    return __fdividef(1.0f, 1.0f + __expf(-x));
}

// Kernel 1: v[b,m] = dot(sigmoid(x[b,1+m,:]), theta)  (one warp per row)
// Also copies the CLS row x[b,0,:] -> out[b,0,:].
__global__ __launch_bounds__(128) void node_score_kernel(
    const float* __restrict__ x, const float* __restrict__ theta,
    float* __restrict__ out)
{
    const int g    = blockIdx.x * 4 + (threadIdx.x >> 5);  // 0..16383
    const int lane = threadIdx.x & 31;
    const int b = g >> 12;
    const int m = g & (NNODES - 1);

    const float* xr = x + ((size_t)b * N1 + 1 + m) * CH;
    float s = 0.0f;
#pragma unroll
    for (int k = 0; k < 3; k++) {
        const int c = lane + 32 * k;
        s += fsig(xr[c]) * theta[c];
    }
#pragma unroll
    for (int off = 16; off > 0; off >>= 1)
        s += __shfl_down_sync(0xffffffffu, s, off);
    if (lane == 0) g_v[g] = s;

    // CLS row copy: 4*96 = 384 elements, handled by the first 3 blocks
    const int idx = blockIdx.x * 128 + threadIdx.x;
    if (idx < BATCH * CH) {
        const int bb = idx / CH, c = idx % CH;
        out[(size_t)bb * (NPATCH + 1) * CH + c] = x[(size_t)bb * N1 * CH + c];
    }
}

// Kernel 2: per patch (b,p): scores for 4 rows = sum_m sigmoid(edge[b,row,m])*v[b,m],
// pick top-1 (first-index tie-break, matching jax top_k). NOTE: the reference
// gathers nodes[b, idx] where idx is the WITHIN-PATCH offset (0..3), not the
// absolute node index — reproduce that exactly.
__global__ __launch_bounds__(256) void score_pool_kernel(
    const float* __restrict__ edge, const float* __restrict__ x,
    float* __restrict__ out)
{
    __shared__ float red[8][4];
    __shared__ float s_scale;
    __shared__ int   s_bidx;

    const int pg = blockIdx.x;         // 0..4095
    const int b  = pg >> 10;
    const int p  = pg & (NPATCH - 1);
    const int tid  = threadIdx.x;
    const int lane = tid & 31;
    const int wid  = tid >> 5;

    const float4* vv4 = (const float4*)(g_v + (b << 12));
    const float4* e0  = (const float4*)(edge + ((size_t)(b << 12) + (p << 2)) * NNODES);
    // row stride in float4 units: 4096/4 = 1024

    float s0 = 0.f, s1 = 0.f, s2 = 0.f, s3 = 0.f;
#pragma unroll
    for (int i = tid; i < 1024; i += 256) {
        const float4 w  = vv4[i];
        const float4 a0 = e0[i];
        const float4 a1 = e0[i + 1024];
        const float4 a2 = e0[i + 2048];
        const float4 a3 = e0[i + 3072];
        s0 += fsig(a0.x)*w.x + fsig(a0.y)*w.y + fsig(a0.z)*w.z + fsig(a0.w)*w.w;
        s1 += fsig(a1.x)*w.x + fsig(a1.y)*w.y + fsig(a1.z)*w.z + fsig(a1.w)*w.w;
        s2 += fsig(a2.x)*w.x + fsig(a2.y)*w.y + fsig(a2.z)*w.z + fsig(a2.w)*w.w;
        s3 += fsig(a3.x)*w.x + fsig(a3.y)*w.y + fsig(a3.z)*w.z + fsig(a3.w)*w.w;
    }

#pragma unroll
    for (int off = 16; off > 0; off >>= 1) {
        s0 += __shfl_down_sync(0xffffffffu, s0, off);
        s1 += __shfl_down_sync(0xffffffffu, s1, off);
        s2 += __shfl_down_sync(0xffffffffu, s2, off);
        s3 += __shfl_down_sync(0xffffffffu, s3, off);
    }
    if (lane == 0) {
        red[wid][0] = s0; red[wid][1] = s1; red[wid][2] = s2; red[wid][3] = s3;
    }
    __syncthreads();

    if (tid == 0) {
        float sc[4];
#pragma unroll
        for (int r = 0; r < 4; r++) {
            float t = 0.f;
#pragma unroll
            for (int w = 0; w < 8; w++) t += red[w][r];
            sc[r] = t;
        }
        // top-1 with lowest-index tie-break (strict >)
        float best = sc[0]; int bi = 0;
#pragma unroll
        for (int r = 1; r < 4; r++)
            if (sc[r] > best) { best = sc[r]; bi = r; }
        s_scale = best + 1.0f;   // pooled = vals*g + g = (vals+1)*g
        s_bidx  = bi;
    }
    __syncthreads();

    if (tid < CH) {
        const int gidx = s_bidx;   // reference uses the raw within-patch index!
        const float g  = x[((size_t)b * N1 + 1 + gidx) * CH + tid];
        out[((size_t)b * (NPATCH + 1) + 1 + p) * CH + tid] = s_scale * g;
    }
}

extern "C" void kernel_launch(void* const* d_in, const int* in_sizes, int n_in,
                              void* d_out, int out_size)
{
    const float* x     = (const float*)d_in[0];  // (4,4097,96) f32
    const float* edge  = (const float*)d_in[1];  // (4,4096,4096) f32
    const float* theta = (const float*)d_in[2];  // (1,96) f32
    float* out = (float*)d_out;                  // (4,1025,96) f32

    node_score_kernel<<<BATCH * NNODES / 4, 128>>>(x, theta, out);
    score_pool_kernel<<<BATCH * NPATCH, 256>>>(edge, x, out);
}